// round 15
// baseline (speedup 1.0000x reference)
#include <cuda_runtime.h>
#include <cstdint>

// ---------------------------------------------------------------------------
// CRSD block: 2-layer leaky reservoir RNN.  B=32, T=1024, D=R=1024, ALPHA=0.1
// v8: v5 pipeline backbone (16KB chunks, NBUF=3, lookahead-2, rotated order,
// grid barriers) but 512 threads / 16 warps per CTA (4 per SMSP) for latency
// hiding. Phase A splits 16 cols between warp halves (0-7: r-cols, 8-15:
// h-cols), 16 rows/chunk/warp -> acc[4], 8-way reduce, RED=4096 floats.
// ---------------------------------------------------------------------------

#define B_DIM 32
#define T_DIM 1024
#define D_DIM 1024
#define TD_STRIDE (T_DIM * T_DIM)
#define GRID_CTAS 128
#define NTHR 512
#define CH 4096                        // chunk: 128 rows x 32 batch = 16KB
#define NBUF 3
#define NCHA 16                        // phase A chunks (8 x + 8 h)
#define NCHB 8                         // phase B chunks

typedef unsigned long long ull;

__device__ float g_buf[(size_t)T_DIM * D_DIM * B_DIM];  // [t][k][b]
__device__ float g_hT[D_DIM * B_DIM];                    // [k][b]
__device__ float g_rT[D_DIM * B_DIM];                    // [k][b]
__device__ unsigned g_bar_count = 0;
__device__ unsigned g_bar_epoch = 0;
__device__ int g_dummy;

// ---- packed fp32x2 helpers -------------------------------------------------
__device__ __forceinline__ ull pk2(float w) {
    ull r;
    asm("mov.b64 %0, {%1, %1};" : "=l"(r) : "f"(w));
    return r;
}
__device__ __forceinline__ void ffma2(ull& acc, ull a, ull w) {
    asm("fma.rn.f32x2 %0, %1, %2, %0;" : "+l"(acc) : "l"(a), "l"(w));
}

// ---- cp.async.cg (L2-sourced => coherent across SMs) ------------------------
__device__ __forceinline__ unsigned smem_u32(const void* p) {
    unsigned a;
    asm("{ .reg .u64 t; cvta.to.shared.u64 t, %1; cvt.u32.u64 %0, t; }"
        : "=r"(a) : "l"(p));
    return a;
}
#define CP_COMMIT_EMPTY() asm volatile("cp.async.commit_group;" ::: "memory")
#define CP_WAIT1()        asm volatile("cp.async.wait_group 1;" ::: "memory")

// copy one 16KB chunk global->smem; 512 threads x 2 x 16B; one group
__device__ __forceinline__ void cp_chunk(float* dst, const float* src, int tid) {
    unsigned sb = smem_u32(dst) + tid * 32;
    const float* gp = src + tid * 8;
    asm volatile("cp.async.cg.shared.global [%0], [%1], 16;"
                 :: "r"(sb), "l"(gp) : "memory");
    asm volatile("cp.async.cg.shared.global [%0], [%1], 16;"
                 :: "r"(sb + 16), "l"(gp + 4) : "memory");
    asm volatile("cp.async.commit_group;" ::: "memory");
}

// ---- grid-wide barrier (128 CTAs co-resident, 1/SM) -------------------------
__device__ __forceinline__ void grid_barrier(unsigned& epoch) {
    __syncthreads();
    if (threadIdx.x == 0) {
        unsigned next = epoch + 1u;
        __threadfence();
        unsigned old = atomicAdd(&g_bar_count, 1u);
        if (old == GRID_CTAS - 1u) {
            atomicExch(&g_bar_count, 0u);
            __threadfence();
            atomicExch(&g_bar_epoch, next);
        } else {
            while (*((volatile unsigned*)&g_bar_epoch) != next) { }
        }
        epoch = next;
    }
    __syncthreads();
}

__device__ __forceinline__ int inc3(int v) { return (v == 2) ? 0 : v + 1; }

// ---------------------------------------------------------------------------
// SMEM: WA[2048][16], WB[1024][8], RED[4096], Ps[256], Rs[256], ACT 3 x 16KB.
// Total = 57856 floats = 231,424 B.
// ---------------------------------------------------------------------------
#define SMEM_FLOATS (2048*16 + 1024*8 + 4096 + 256 + 256 + NBUF*CH)
#define SMEM_BYTES  (SMEM_FLOATS * 4)

__global__ void __launch_bounds__(NTHR, 1)
scan_kernel(const float* __restrict__ Wxh, const float* __restrict__ Whh,
            const float* __restrict__ Wrh, const float* __restrict__ Wxr,
            const float* __restrict__ Whr, int layer)
{
    extern __shared__ float sm[];
    float* WA  = sm;                        // 2048*16
    float* WB  = WA + 2048 * 16;            // 1024*8
    float* RED = WB + 1024 * 8;             // 4096
    float* Ps  = RED + 4096;                // 256
    float* Rs  = Ps + 256;                  // 256
    float* ACT = Rs + 256;                  // 3*4096

    const int tid  = threadIdx.x;
    const int cta  = blockIdx.x;
    const int c8   = cta * 8;
    const int lane = tid & 31;
    const int warp = tid >> 5;              // 0..15
    const int w8   = warp & 7;
    const int rot  = cta & 7;

    const size_t DR = (size_t)D_DIM * D_DIM;
    const float* wxh = Wxh + (size_t)layer * DR;
    const float* whh = Whh + (size_t)layer * DR;
    const float* wrh = Wrh + (size_t)layer * DR;
    const float* wxr = Wxr + (size_t)layer * DR;
    const float* whr = Whr + (size_t)layer * DR;

    // ---- weight slices -> SMEM (once per layer) ----
    for (int i = tid; i < 8192; i += NTHR) {
        int k  = i >> 3;
        int jc = i & 7;
        int g  = k * D_DIM + c8 + jc;
        WA[k * 16 + jc]              = wxr[g];
        WA[k * 16 + 8 + jc]          = wxh[g];
        WA[(k + 1024) * 16 + jc]     = whr[g];
        WA[(k + 1024) * 16 + 8 + jc] = whh[g];
        WB[k * 8 + jc]               = wrh[g];
    }
    // ---- zero state ----
    if (tid < 256) {
        Rs[tid] = 0.0f;
        int j = tid >> 5, b = tid & 31;
        g_hT[(c8 + j) * 32 + b] = 0.0f;
    }
    unsigned epoch = *((volatile unsigned*)&g_bar_epoch);
    __threadfence();
    grid_barrier(epoch);

    const int jj = lane >> 2;   // 0..7 : column within the warp's 8-col group
    const int bb = lane & 3;    // 0..3 : batch octet
    // phase A column offset in WA row: warps 0-7 -> cols 0-7 (r), 8-15 -> 8-15 (h)
    const int colA = (warp < 8) ? jj : (8 + jj);

    auto ciA = [&](int c) -> int {
        return (c < 8) ? ((c + rot) & 7) : (8 + ((c + rot) & 7));
    };
    auto ciB = [&](int c) -> int { return (c + rot) & 7; };

    int ibuf = 0, cbuf = 0;

    // ---- t=0 phase-A prologue: chunks A0, A1 (x-half) ----
    cp_chunk(ACT + ibuf * CH, g_buf + ciA(0) * CH, tid); ibuf = inc3(ibuf);
    cp_chunk(ACT + ibuf * CH, g_buf + ciA(1) * CH, tid); ibuf = inc3(ibuf);

    for (int t = 0; t < T_DIM; ++t) {
        const float* xsrc = g_buf + (size_t)t * (D_DIM * B_DIM);

        // ================= PHASE A =================
        // U[32,16] = [x_t ; h](32x2048) @ WA(2048x16); 16 chunks of 128 rows.
        // Warp w handles rows (w&7)*16..+15 of each chunk for its 8 columns.
        {
            ull acc[4];
            #pragma unroll
            for (int i = 0; i < 4; ++i) acc[i] = 0ULL;

            #pragma unroll 1
            for (int c = 0; c < NCHA; ++c) {
                CP_WAIT1();
                __syncthreads();

                int nc = c + 2;
                if (nc < NCHA) {
                    int cin = ciA(nc);
                    const float* src = (cin < 8)
                        ? (xsrc + cin * CH)
                        : (g_hT + (cin - 8) * CH);
                    cp_chunk(ACT + ibuf * CH, src, tid);
                    ibuf = inc3(ibuf);
                } else {
                    CP_COMMIT_EMPTY();
                }

                int ci = ciA(c);
                const float* cb   = ACT + cbuf * CH;
                cbuf = inc3(cbuf);
                const float* arow = cb + w8 * (16 * 32) + bb * 8;
                const float* wcol = WA + (ci * 128 + w8 * 16) * 16 + colA;

                #pragma unroll
                for (int kl = 0; kl < 16; ++kl) {
                    ulonglong2 a01 = *(const ulonglong2*)(arow + kl * 32);
                    ulonglong2 a23 = *(const ulonglong2*)(arow + kl * 32 + 4);
                    ull wp = pk2(wcol[kl * 16]);
                    ffma2(acc[0], a01.x, wp);
                    ffma2(acc[1], a01.y, wp);
                    ffma2(acc[2], a23.x, wp);
                    ffma2(acc[3], a23.y, wp);
                }
            }

            // stash: RED[warp][jj][b]  (warps 0-7: cols 0-7, 8-15: cols 8-15)
            float* rw = RED + warp * 256;
            ull* p0 = (ull*)(rw + jj * 32 + bb * 8);
            p0[0] = acc[0]; p0[1] = acc[1]; p0[2] = acc[2]; p0[3] = acc[3];
        }
        __syncthreads();
        // reduce A: 512 outputs (16 cols x 32 b), one per thread, 8-way sum
        {
            int o = tid;                 // o = j*32 + b, j in 0..15
            int j = o >> 5, b = o & 31;
            float s = 0.0f;
            if (j < 8) {
                #pragma unroll
                for (int w = 0; w < 8; ++w) s += RED[w * 256 + j * 32 + b];
                float g  = tanhf(s);
                int   lo = j * 32 + b;
                float rn = 0.9f * Rs[lo] + 0.1f * g;
                Rs[lo] = rn;
                g_rT[(c8 + j) * 32 + b] = rn;
            } else {
                #pragma unroll
                for (int w = 8; w < 16; ++w) s += RED[w * 256 + (j - 8) * 32 + b];
                Ps[(j - 8) * 32 + b] = s;
            }
        }
        __threadfence();
        grid_barrier(epoch);   // r_new globally visible

        // ================= PHASE B =================
        // Z[32,8] = r_new(32x1024) @ WB(1024x8); 8 chunks of 128 rows.
        // Warp w handles rows w*8..w*8+7 of each chunk, all 8 cols.
        {
            cp_chunk(ACT + ibuf * CH, g_rT + ciB(0) * CH, tid); ibuf = inc3(ibuf);
            cp_chunk(ACT + ibuf * CH, g_rT + ciB(1) * CH, tid); ibuf = inc3(ibuf);

            ull acc[4];
            #pragma unroll
            for (int i = 0; i < 4; ++i) acc[i] = 0ULL;

            #pragma unroll 1
            for (int c = 0; c < NCHB; ++c) {
                CP_WAIT1();
                __syncthreads();

                int nc = c + 2;
                if (nc < NCHB) {
                    cp_chunk(ACT + ibuf * CH, g_rT + ciB(nc) * CH, tid);
                    ibuf = inc3(ibuf);
                } else if (t + 1 < T_DIM) {
                    // cross-step prefetch: next step's A chunks 0,1 (x-half)
                    const float* nx = g_buf + (size_t)(t + 1) * (D_DIM * B_DIM);
                    cp_chunk(ACT + ibuf * CH, nx + ciA(nc - NCHB) * CH, tid);
                    ibuf = inc3(ibuf);
                } else {
                    CP_COMMIT_EMPTY();
                }

                int ci = ciB(c);
                const float* cb   = ACT + cbuf * CH;
                cbuf = inc3(cbuf);
                const float* arow = cb + warp * (8 * 32) + bb * 8;
                const float* wcol = WB + (ci * 128 + warp * 8) * 8 + jj;

                #pragma unroll
                for (int kl = 0; kl < 8; ++kl) {
                    ulonglong2 a01 = *(const ulonglong2*)(arow + kl * 32);
                    ulonglong2 a23 = *(const ulonglong2*)(arow + kl * 32 + 4);
                    ull wp = pk2(wcol[kl * 8]);
                    ffma2(acc[0], a01.x, wp);
                    ffma2(acc[1], a01.y, wp);
                    ffma2(acc[2], a23.x, wp);
                    ffma2(acc[3], a23.y, wp);
                }
            }

            float* rw = RED + warp * 256;
            ull* p0 = (ull*)(rw + jj * 32 + bb * 8);
            p0[0] = acc[0]; p0[1] = acc[1]; p0[2] = acc[2]; p0[3] = acc[3];
        }
        __syncthreads();
        // reduce B (16-way) + h update: 256 outputs
        if (tid < 256) {
            float z = 0.0f;
            #pragma unroll
            for (int w = 0; w < 16; ++w) z += RED[w * 256 + tid];
            int j = tid >> 5, b = tid & 31;
            float hn = tanhf(Ps[tid] + z);
            g_hT[(c8 + j) * 32 + b] = hn;
            g_buf[(size_t)t * (D_DIM * B_DIM) + (c8 + j) * 32 + b] = hn;
        }
        __threadfence();
        grid_barrier(epoch);   // h_new visible before next step
    }
}

// ---------------------------------------------------------------------------
// Dummy kernel (ncu launch-index alignment so -s 5 -c 1 lands on scan_kernel)
// ---------------------------------------------------------------------------
__global__ void dummy_k(int v) { if (threadIdx.x == 0) g_dummy = v; }

// ---------------------------------------------------------------------------
// Transposes: x[b][t][k]  <->  buf[t][k][b]
// ---------------------------------------------------------------------------
__global__ void transpose_in(const float* __restrict__ x)
{
    __shared__ float s[32][65];
    const int t  = blockIdx.y;
    const int k0 = blockIdx.x * 64;
    const int tid = threadIdx.x;

    #pragma unroll
    for (int p = 0; p < 8; ++p) {
        int b  = p * 4 + (tid >> 6);
        int kk = tid & 63;
        s[b][kk] = x[(size_t)b * TD_STRIDE + (size_t)t * D_DIM + k0 + kk];
    }
    __syncthreads();
    #pragma unroll
    for (int p = 0; p < 8; ++p) {
        int kk = p * 8 + (tid >> 5);
        int b  = tid & 31;
        g_buf[(size_t)t * (D_DIM * B_DIM) + (size_t)(k0 + kk) * 32 + b] = s[b][kk];
    }
}

__global__ void transpose_out(float* __restrict__ out)
{
    __shared__ float s[64][33];
    const int t  = blockIdx.y;
    const int j0 = blockIdx.x * 64;
    const int tid = threadIdx.x;

    #pragma unroll
    for (int p = 0; p < 8; ++p) {
        int jj = p * 8 + (tid >> 5);
        int b  = tid & 31;
        s[jj][b] = g_buf[(size_t)t * (D_DIM * B_DIM) + (size_t)(j0 + jj) * 32 + b];
    }
    __syncthreads();
    #pragma unroll
    for (int p = 0; p < 8; ++p) {
        int b  = p * 4 + (tid >> 6);
        int jc = tid & 63;
        out[(size_t)b * TD_STRIDE + (size_t)t * D_DIM + j0 + jc] = s[jc][b];
    }
}

// ---------------------------------------------------------------------------
extern "C" void kernel_launch(void* const* d_in, const int* in_sizes, int n_in,
                              void* d_out, int out_size)
{
    const float* x   = (const float*)d_in[0];
    const float* Wxh = (const float*)d_in[1];
    const float* Whh = (const float*)d_in[2];
    const float* Wrh = (const float*)d_in[3];
    const float* Wxr = (const float*)d_in[4];
    const float* Whr = (const float*)d_in[5];
    float* out = (float*)d_out;

    cudaFuncSetAttribute(scan_kernel,
                         cudaFuncAttributeMaxDynamicSharedMemorySize,
                         SMEM_BYTES);

    dummy_k<<<1, 32>>>(1);
    dummy_k<<<1, 32>>>(2);
    transpose_in<<<dim3(16, 1024), 256>>>(x);
    scan_kernel<<<GRID_CTAS, NTHR, SMEM_BYTES>>>(Wxh, Whh, Wrh, Wxr, Whr, 0);
    scan_kernel<<<GRID_CTAS, NTHR, SMEM_BYTES>>>(Wxh, Whh, Wrh, Wxr, Whr, 1);
    transpose_out<<<dim3(16, 1024), 256>>>(out);
}

// round 16
// speedup vs baseline: 1.9459x; 1.9459x over previous
#include <cuda_runtime.h>
#include <cstdint>

// ---------------------------------------------------------------------------
// CRSD block: 2-layer leaky reservoir RNN.  B=32, T=1024, D=R=1024, ALPHA=0.1
// v9: v5 backbone (256 thr, 16KB chunks, NBUF=3, rotated order, grid barriers)
// with re-tiled compute for full-width LDS wavefronts: thread = (jg, bb) owns
// a 4-col x 4-batch register tile; activation LDS.128 is 8x16B distinct
// (128B/wavefront) and weights load as one LDS.128 (4 cols) per k-row.
// Target: the measured L1tex-port bottleneck (52-62% busy in R14/R15).
// ---------------------------------------------------------------------------

#define B_DIM 32
#define T_DIM 1024
#define D_DIM 1024
#define TD_STRIDE (T_DIM * T_DIM)
#define GRID_CTAS 128
#define NTHR 256
#define CH 4096                        // chunk: 128 rows x 32 batch = 16KB
#define NBUF 3
#define NCHA 16                        // phase A chunks (8 x + 8 h)
#define NCHB 8                         // phase B chunks

typedef unsigned long long ull;

__device__ float g_buf[(size_t)T_DIM * D_DIM * B_DIM];  // [t][k][b]
__device__ float g_hT[D_DIM * B_DIM];                    // [k][b]
__device__ float g_rT[D_DIM * B_DIM];                    // [k][b]
__device__ unsigned g_bar_count = 0;
__device__ unsigned g_bar_epoch = 0;
__device__ int g_dummy;

// ---- packed fp32x2 helpers -------------------------------------------------
__device__ __forceinline__ ull pk2(float w) {
    ull r;
    asm("mov.b64 %0, {%1, %1};" : "=l"(r) : "f"(w));
    return r;
}
__device__ __forceinline__ void ffma2(ull& acc, ull a, ull w) {
    asm("fma.rn.f32x2 %0, %1, %2, %0;" : "+l"(acc) : "l"(a), "l"(w));
}

// ---- cp.async.cg (L2-sourced => coherent across SMs) ------------------------
__device__ __forceinline__ unsigned smem_u32(const void* p) {
    unsigned a;
    asm("{ .reg .u64 t; cvta.to.shared.u64 t, %1; cvt.u32.u64 %0, t; }"
        : "=r"(a) : "l"(p));
    return a;
}
#define CP_COMMIT_EMPTY() asm volatile("cp.async.commit_group;" ::: "memory")
#define CP_WAIT1()        asm volatile("cp.async.wait_group 1;" ::: "memory")

// copy one 16KB chunk global->smem; 256 threads x 4 x 16B; one group
__device__ __forceinline__ void cp_chunk(float* dst, const float* src, int tid) {
    unsigned sb = smem_u32(dst) + tid * 16;
    const float* gp = src + tid * 4;
    #pragma unroll
    for (int i = 0; i < 4; ++i) {
        asm volatile("cp.async.cg.shared.global [%0], [%1], 16;"
                     :: "r"(sb + i * 4096), "l"(gp + i * 1024) : "memory");
    }
    asm volatile("cp.async.commit_group;" ::: "memory");
}

// ---- grid-wide barrier (128 CTAs co-resident, 1/SM) -------------------------
__device__ __forceinline__ void grid_barrier(unsigned& epoch) {
    __syncthreads();
    if (threadIdx.x == 0) {
        unsigned next = epoch + 1u;
        __threadfence();
        unsigned old = atomicAdd(&g_bar_count, 1u);
        if (old == GRID_CTAS - 1u) {
            atomicExch(&g_bar_count, 0u);
            __threadfence();
            atomicExch(&g_bar_epoch, next);
        } else {
            while (*((volatile unsigned*)&g_bar_epoch) != next) { }
        }
        epoch = next;
    }
    __syncthreads();
}

__device__ __forceinline__ int inc3(int v) { return (v == 2) ? 0 : v + 1; }

// ---------------------------------------------------------------------------
// SMEM: WA[2048][16], WB[1024][8], RED[4096], Ps[256], Rs[256], ACT 3 x 16KB.
// Total = 57856 floats = 231,424 B.
// ---------------------------------------------------------------------------
#define SMEM_FLOATS (2048*16 + 1024*8 + 4096 + 256 + 256 + NBUF*CH)
#define SMEM_BYTES  (SMEM_FLOATS * 4)

__global__ void __launch_bounds__(NTHR, 1)
scan_kernel(const float* __restrict__ Wxh, const float* __restrict__ Whh,
            const float* __restrict__ Wrh, const float* __restrict__ Wxr,
            const float* __restrict__ Whr, int layer)
{
    extern __shared__ float sm[];
    float* WA  = sm;                        // 2048*16
    float* WB  = WA + 2048 * 16;            // 1024*8
    float* RED = WB + 1024 * 8;             // 4096
    float* Ps  = RED + 4096;                // 256
    float* Rs  = Ps + 256;                  // 256
    float* ACT = Rs + 256;                  // 3*4096

    const int tid  = threadIdx.x;
    const int cta  = blockIdx.x;
    const int c8   = cta * 8;
    const int lane = tid & 31;
    const int warp = tid >> 5;
    const int rot  = cta & 7;

    const size_t DR = (size_t)D_DIM * D_DIM;
    const float* wxh = Wxh + (size_t)layer * DR;
    const float* whh = Whh + (size_t)layer * DR;
    const float* wrh = Wrh + (size_t)layer * DR;
    const float* wxr = Wxr + (size_t)layer * DR;
    const float* whr = Whr + (size_t)layer * DR;

    // ---- weight slices -> SMEM (once per layer) ----
    for (int i = tid; i < 8192; i += NTHR) {
        int k  = i >> 3;
        int jc = i & 7;
        int g  = k * D_DIM + c8 + jc;
        WA[k * 16 + jc]              = wxr[g];
        WA[k * 16 + 8 + jc]          = wxh[g];
        WA[(k + 1024) * 16 + jc]     = whr[g];
        WA[(k + 1024) * 16 + 8 + jc] = whh[g];
        WB[k * 8 + jc]               = wrh[g];
    }
    // ---- zero state ----
    {
        Rs[tid] = 0.0f;
        int j = tid >> 5, b = tid & 31;
        g_hT[(c8 + j) * 32 + b] = 0.0f;
    }
    unsigned epoch = *((volatile unsigned*)&g_bar_epoch);
    __threadfence();
    grid_barrier(epoch);

    const int jg = lane >> 3;   // 0..3 : column group (4 cols each)
    const int bb = lane & 7;    // 0..7 : batch quad (4 floats)

    auto ciA = [&](int c) -> int {
        return (c < 8) ? ((c + rot) & 7) : (8 + ((c + rot) & 7));
    };
    auto ciB = [&](int c) -> int { return (c + rot) & 7; };

    int ibuf = 0, cbuf = 0;

    // ---- t=0 phase-A prologue: chunks A0, A1 (x-half) ----
    cp_chunk(ACT + ibuf * CH, g_buf + ciA(0) * CH, tid); ibuf = inc3(ibuf);
    cp_chunk(ACT + ibuf * CH, g_buf + ciA(1) * CH, tid); ibuf = inc3(ibuf);

    for (int t = 0; t < T_DIM; ++t) {
        const float* xsrc = g_buf + (size_t)t * (D_DIM * B_DIM);

        // ================= PHASE A =================
        // U[32,16] = [x_t ; h](32x2048) @ WA(2048x16); 16 chunks of 128 rows.
        // Warp w: rows w*16..+15. Thread (jg,bb): cols jg*4..+3, b = bb*4..+3.
        {
            ull acc[8];                     // [col 0..3][batch pair 0..1]
            #pragma unroll
            for (int i = 0; i < 8; ++i) acc[i] = 0ULL;

            #pragma unroll 1
            for (int c = 0; c < NCHA; ++c) {
                CP_WAIT1();
                __syncthreads();

                int nc = c + 2;
                if (nc < NCHA) {
                    int cin = ciA(nc);
                    const float* src = (cin < 8)
                        ? (xsrc + cin * CH)
                        : (g_hT + (cin - 8) * CH);
                    cp_chunk(ACT + ibuf * CH, src, tid);
                    ibuf = inc3(ibuf);
                } else {
                    CP_COMMIT_EMPTY();
                }

                int ci = ciA(c);
                const float* cb   = ACT + cbuf * CH;
                cbuf = inc3(cbuf);
                const float* arow = cb + warp * (16 * 32) + bb * 4;
                const float* wrow = WA + (ci * 128 + warp * 16) * 16 + jg * 4;

                #pragma unroll
                for (int kl = 0; kl < 16; ++kl) {
                    ulonglong2 a = *(const ulonglong2*)(arow + kl * 32);
                    float4 wv    = *(const float4*)(wrow + kl * 16);
                    ull wp0 = pk2(wv.x);
                    ull wp1 = pk2(wv.y);
                    ull wp2 = pk2(wv.z);
                    ull wp3 = pk2(wv.w);
                    ffma2(acc[0], a.x, wp0);
                    ffma2(acc[1], a.y, wp0);
                    ffma2(acc[2], a.x, wp1);
                    ffma2(acc[3], a.y, wp1);
                    ffma2(acc[4], a.x, wp2);
                    ffma2(acc[5], a.y, wp2);
                    ffma2(acc[6], a.x, wp3);
                    ffma2(acc[7], a.y, wp3);
                }
            }

            // stash: RED[warp][j][b], j = jg*4+cl
            float* rw = RED + warp * 512;
            #pragma unroll
            for (int cl = 0; cl < 4; ++cl) {
                ull* p = (ull*)(rw + (jg * 4 + cl) * 32 + bb * 4);
                p[0] = acc[cl * 2];
                p[1] = acc[cl * 2 + 1];
            }
        }
        __syncthreads();
        // cross-warp reduce + r update / p stash (512 outputs, 8-way)
        #pragma unroll
        for (int o = tid; o < 512; o += NTHR) {
            float s = 0.0f;
            #pragma unroll
            for (int w = 0; w < 8; ++w) s += RED[w * 512 + o];
            int j = o >> 5, b = o & 31;
            if (j < 8) {
                float g  = tanhf(s);
                float rn = 0.9f * Rs[o] + 0.1f * g;
                Rs[o] = rn;
                g_rT[(c8 + j) * 32 + b] = rn;
            } else {
                Ps[o - 256] = s;
            }
        }
        __threadfence();
        grid_barrier(epoch);   // r_new globally visible

        // ================= PHASE B =================
        // Z[32,8] = r_new(32x1024) @ WB(1024x8); 8 chunks of 128 rows.
        // Thread (jg,bb): cols jg*2..+1, b = bb*4..+3.
        {
            cp_chunk(ACT + ibuf * CH, g_rT + ciB(0) * CH, tid); ibuf = inc3(ibuf);
            cp_chunk(ACT + ibuf * CH, g_rT + ciB(1) * CH, tid); ibuf = inc3(ibuf);

            ull acc[4];                     // [col 0..1][batch pair 0..1]
            #pragma unroll
            for (int i = 0; i < 4; ++i) acc[i] = 0ULL;

            #pragma unroll 1
            for (int c = 0; c < NCHB; ++c) {
                CP_WAIT1();
                __syncthreads();

                int nc = c + 2;
                if (nc < NCHB) {
                    cp_chunk(ACT + ibuf * CH, g_rT + ciB(nc) * CH, tid);
                    ibuf = inc3(ibuf);
                } else if (t + 1 < T_DIM) {
                    const float* nx = g_buf + (size_t)(t + 1) * (D_DIM * B_DIM);
                    cp_chunk(ACT + ibuf * CH, nx + ciA(nc - NCHB) * CH, tid);
                    ibuf = inc3(ibuf);
                } else {
                    CP_COMMIT_EMPTY();
                }

                int ci = ciB(c);
                const float* cb   = ACT + cbuf * CH;
                cbuf = inc3(cbuf);
                const float* arow = cb + warp * (16 * 32) + bb * 4;
                const float* wrow = WB + (ci * 128 + warp * 16) * 8 + jg * 2;

                #pragma unroll
                for (int kl = 0; kl < 16; ++kl) {
                    ulonglong2 a = *(const ulonglong2*)(arow + kl * 32);
                    float2 wv    = *(const float2*)(wrow + kl * 8);
                    ull wp0 = pk2(wv.x);
                    ull wp1 = pk2(wv.y);
                    ffma2(acc[0], a.x, wp0);
                    ffma2(acc[1], a.y, wp0);
                    ffma2(acc[2], a.x, wp1);
                    ffma2(acc[3], a.y, wp1);
                }
            }

            float* rw = RED + warp * 256;
            #pragma unroll
            for (int cl = 0; cl < 2; ++cl) {
                ull* p = (ull*)(rw + (jg * 2 + cl) * 32 + bb * 4);
                p[0] = acc[cl * 2];
                p[1] = acc[cl * 2 + 1];
            }
        }
        __syncthreads();
        {
            float z = 0.0f;
            #pragma unroll
            for (int w = 0; w < 8; ++w) z += RED[w * 256 + tid];
            int j = tid >> 5, b = tid & 31;
            float hn = tanhf(Ps[tid] + z);
            g_hT[(c8 + j) * 32 + b] = hn;
            g_buf[(size_t)t * (D_DIM * B_DIM) + (c8 + j) * 32 + b] = hn;
        }
        __threadfence();
        grid_barrier(epoch);   // h_new visible before next step
    }
}

// ---------------------------------------------------------------------------
// Dummy kernel (ncu launch-index alignment so -s 5 -c 1 lands on scan_kernel)
// ---------------------------------------------------------------------------
__global__ void dummy_k(int v) { if (threadIdx.x == 0) g_dummy = v; }

// ---------------------------------------------------------------------------
// Transposes: x[b][t][k]  <->  buf[t][k][b]
// ---------------------------------------------------------------------------
__global__ void transpose_in(const float* __restrict__ x)
{
    __shared__ float s[32][65];
    const int t  = blockIdx.y;
    const int k0 = blockIdx.x * 64;
    const int tid = threadIdx.x;

    #pragma unroll
    for (int p = 0; p < 8; ++p) {
        int b  = p * 4 + (tid >> 6);
        int kk = tid & 63;
        s[b][kk] = x[(size_t)b * TD_STRIDE + (size_t)t * D_DIM + k0 + kk];
    }
    __syncthreads();
    #pragma unroll
    for (int p = 0; p < 8; ++p) {
        int kk = p * 8 + (tid >> 5);
        int b  = tid & 31;
        g_buf[(size_t)t * (D_DIM * B_DIM) + (size_t)(k0 + kk) * 32 + b] = s[b][kk];
    }
}

__global__ void transpose_out(float* __restrict__ out)
{
    __shared__ float s[64][33];
    const int t  = blockIdx.y;
    const int j0 = blockIdx.x * 64;
    const int tid = threadIdx.x;

    #pragma unroll
    for (int p = 0; p < 8; ++p) {
        int jj = p * 8 + (tid >> 5);
        int b  = tid & 31;
        s[jj][b] = g_buf[(size_t)t * (D_DIM * B_DIM) + (size_t)(j0 + jj) * 32 + b];
    }
    __syncthreads();
    #pragma unroll
    for (int p = 0; p < 8; ++p) {
        int b  = p * 4 + (tid >> 6);
        int jc = tid & 63;
        out[(size_t)b * TD_STRIDE + (size_t)t * D_DIM + j0 + jc] = s[jc][b];
    }
}

// ---------------------------------------------------------------------------
extern "C" void kernel_launch(void* const* d_in, const int* in_sizes, int n_in,
                              void* d_out, int out_size)
{
    const float* x   = (const float*)d_in[0];
    const float* Wxh = (const float*)d_in[1];
    const float* Whh = (const float*)d_in[2];
    const float* Wrh = (const float*)d_in[3];
    const float* Wxr = (const float*)d_in[4];
    const float* Whr = (const float*)d_in[5];
    float* out = (float*)d_out;

    cudaFuncSetAttribute(scan_kernel,
                         cudaFuncAttributeMaxDynamicSharedMemorySize,
                         SMEM_BYTES);

    dummy_k<<<1, 32>>>(1);
    dummy_k<<<1, 32>>>(2);
    transpose_in<<<dim3(16, 1024), NTHR>>>(x);
    scan_kernel<<<GRID_CTAS, NTHR, SMEM_BYTES>>>(Wxh, Whh, Wrh, Wxr, Whr, 0);
    scan_kernel<<<GRID_CTAS, NTHR, SMEM_BYTES>>>(Wxh, Whh, Wrh, Wxr, Whr, 1);
    transpose_out<<<dim3(16, 1024), NTHR>>>(out);
}

// round 17
// speedup vs baseline: 1.9504x; 1.0023x over previous
#include <cuda_runtime.h>
#include <cstdint>

// ---------------------------------------------------------------------------
// CRSD block: 2-layer leaky reservoir RNN.  B=32, T=1024, D=R=1024, ALPHA=0.1
// v10: v9 backbone (256 thr, 16KB chunks, NBUF=3, rotation, grid barriers)
// with a deeper register tile: lane = (rr, jg, bh); each thread computes
// 4 cols x 8 batch over 8 rows/chunk (rows split 2-way in-warp, merged by a
// shfl-bfly f32x2 reduce once per phase). Per kl: 16 FFMA2, 4 pk2, 3 LDS
// (all full 128B wavefronts) -> issue -23%, L1 wavefronts -25% vs v9.
// ---------------------------------------------------------------------------

#define B_DIM 32
#define T_DIM 1024
#define D_DIM 1024
#define TD_STRIDE (T_DIM * T_DIM)
#define GRID_CTAS 128
#define NTHR 256
#define CH 4096                        // chunk: 128 rows x 32 batch = 16KB
#define NBUF 3
#define NCHA 16                        // phase A chunks (8 x + 8 h)
#define NCHB 8                         // phase B chunks

typedef unsigned long long ull;

__device__ float g_buf[(size_t)T_DIM * D_DIM * B_DIM];  // [t][k][b]
__device__ float g_hT[D_DIM * B_DIM];                    // [k][b]
__device__ float g_rT[D_DIM * B_DIM];                    // [k][b]
__device__ unsigned g_bar_count = 0;
__device__ unsigned g_bar_epoch = 0;
__device__ int g_dummy;

// ---- packed fp32x2 helpers -------------------------------------------------
__device__ __forceinline__ ull pk2(float w) {
    ull r;
    asm("mov.b64 %0, {%1, %1};" : "=l"(r) : "f"(w));
    return r;
}
__device__ __forceinline__ void ffma2(ull& acc, ull a, ull w) {
    asm("fma.rn.f32x2 %0, %1, %2, %0;" : "+l"(acc) : "l"(a), "l"(w));
}
__device__ __forceinline__ ull addf2(ull a, ull b) {
    ull r;
    asm("add.rn.f32x2 %0, %1, %2;" : "=l"(r) : "l"(a), "l"(b));
    return r;
}
// reduce across rr halves (lane ^ 16): both halves end with the full sum
__device__ __forceinline__ ull red16(ull v) {
    unsigned lo = (unsigned)v, hi = (unsigned)(v >> 32);
    lo = __shfl_xor_sync(0xffffffffu, lo, 16);
    hi = __shfl_xor_sync(0xffffffffu, hi, 16);
    return addf2(v, ((ull)hi << 32) | (ull)lo);
}

// ---- cp.async.cg (L2-sourced => coherent across SMs) ------------------------
__device__ __forceinline__ unsigned smem_u32(const void* p) {
    unsigned a;
    asm("{ .reg .u64 t; cvta.to.shared.u64 t, %1; cvt.u32.u64 %0, t; }"
        : "=r"(a) : "l"(p));
    return a;
}
#define CP_COMMIT_EMPTY() asm volatile("cp.async.commit_group;" ::: "memory")
#define CP_WAIT1()        asm volatile("cp.async.wait_group 1;" ::: "memory")

// copy one 16KB chunk global->smem; 256 threads x 4 x 16B; one group
__device__ __forceinline__ void cp_chunk(float* dst, const float* src, int tid) {
    unsigned sb = smem_u32(dst) + tid * 16;
    const float* gp = src + tid * 4;
    #pragma unroll
    for (int i = 0; i < 4; ++i) {
        asm volatile("cp.async.cg.shared.global [%0], [%1], 16;"
                     :: "r"(sb + i * 4096), "l"(gp + i * 1024) : "memory");
    }
    asm volatile("cp.async.commit_group;" ::: "memory");
}

// ---- grid-wide barrier (128 CTAs co-resident, 1/SM) -------------------------
__device__ __forceinline__ void grid_barrier(unsigned& epoch) {
    __syncthreads();
    if (threadIdx.x == 0) {
        unsigned next = epoch + 1u;
        __threadfence();
        unsigned old = atomicAdd(&g_bar_count, 1u);
        if (old == GRID_CTAS - 1u) {
            atomicExch(&g_bar_count, 0u);
            __threadfence();
            atomicExch(&g_bar_epoch, next);
        } else {
            while (*((volatile unsigned*)&g_bar_epoch) != next) { }
        }
        epoch = next;
    }
    __syncthreads();
}

__device__ __forceinline__ int inc3(int v) { return (v == 2) ? 0 : v + 1; }

// ---------------------------------------------------------------------------
// SMEM: WA[2048][16], WB[1024][8], RED[4096], Ps[256], Rs[256], ACT 3 x 16KB.
// Total = 57856 floats = 231,424 B.
// ---------------------------------------------------------------------------
#define SMEM_FLOATS (2048*16 + 1024*8 + 4096 + 256 + 256 + NBUF*CH)
#define SMEM_BYTES  (SMEM_FLOATS * 4)

__global__ void __launch_bounds__(NTHR, 1)
scan_kernel(const float* __restrict__ Wxh, const float* __restrict__ Whh,
            const float* __restrict__ Wrh, const float* __restrict__ Wxr,
            const float* __restrict__ Whr, int layer)
{
    extern __shared__ float sm[];
    float* WA  = sm;                        // 2048*16
    float* WB  = WA + 2048 * 16;            // 1024*8
    float* RED = WB + 1024 * 8;             // 4096
    float* Ps  = RED + 4096;                // 256
    float* Rs  = Ps + 256;                  // 256
    float* ACT = Rs + 256;                  // 3*4096

    const int tid  = threadIdx.x;
    const int cta  = blockIdx.x;
    const int c8   = cta * 8;
    const int lane = tid & 31;
    const int warp = tid >> 5;
    const int rot  = cta & 7;

    const size_t DR = (size_t)D_DIM * D_DIM;
    const float* wxh = Wxh + (size_t)layer * DR;
    const float* whh = Whh + (size_t)layer * DR;
    const float* wrh = Wrh + (size_t)layer * DR;
    const float* wxr = Wxr + (size_t)layer * DR;
    const float* whr = Whr + (size_t)layer * DR;

    // ---- weight slices -> SMEM (once per layer) ----
    for (int i = tid; i < 8192; i += NTHR) {
        int k  = i >> 3;
        int jc = i & 7;
        int g  = k * D_DIM + c8 + jc;
        WA[k * 16 + jc]              = wxr[g];
        WA[k * 16 + 8 + jc]          = wxh[g];
        WA[(k + 1024) * 16 + jc]     = whr[g];
        WA[(k + 1024) * 16 + 8 + jc] = whh[g];
        WB[k * 8 + jc]               = wrh[g];
    }
    // ---- zero state ----
    {
        Rs[tid] = 0.0f;
        int j = tid >> 5, b = tid & 31;
        g_hT[(c8 + j) * 32 + b] = 0.0f;
    }
    unsigned epoch = *((volatile unsigned*)&g_bar_epoch);
    __threadfence();
    grid_barrier(epoch);

    // lane decomposition: rr = row half, jg = col group, bh = batch octet
    const int rr = lane >> 4;          // 0..1
    const int jg = (lane >> 2) & 3;    // 0..3
    const int bh = lane & 3;           // 0..3

    auto ciA = [&](int c) -> int {
        return (c < 8) ? ((c + rot) & 7) : (8 + ((c + rot) & 7));
    };
    auto ciB = [&](int c) -> int { return (c + rot) & 7; };

    int ibuf = 0, cbuf = 0;

    // ---- t=0 phase-A prologue: chunks A0, A1 (x-half) ----
    cp_chunk(ACT + ibuf * CH, g_buf + ciA(0) * CH, tid); ibuf = inc3(ibuf);
    cp_chunk(ACT + ibuf * CH, g_buf + ciA(1) * CH, tid); ibuf = inc3(ibuf);

    for (int t = 0; t < T_DIM; ++t) {
        const float* xsrc = g_buf + (size_t)t * (D_DIM * B_DIM);

        // ================= PHASE A =================
        // U[32,16] = [x_t ; h](32x2048) @ WA(2048x16); 16 chunks of 128 rows.
        // Warp w: rows w*16..+15; thread (rr,jg,bh): rows w*16+rr*8..+7,
        // cols jg*4..+3, batch bh*8..+7.
        {
            ull acc[16];                    // [cl 0..3][pair 0..3]
            #pragma unroll
            for (int i = 0; i < 16; ++i) acc[i] = 0ULL;

            #pragma unroll 1
            for (int c = 0; c < NCHA; ++c) {
                CP_WAIT1();
                __syncthreads();

                int nc = c + 2;
                if (nc < NCHA) {
                    int cin = ciA(nc);
                    const float* src = (cin < 8)
                        ? (xsrc + cin * CH)
                        : (g_hT + (cin - 8) * CH);
                    cp_chunk(ACT + ibuf * CH, src, tid);
                    ibuf = inc3(ibuf);
                } else {
                    CP_COMMIT_EMPTY();
                }

                int ci = ciA(c);
                const float* cb   = ACT + cbuf * CH;
                cbuf = inc3(cbuf);
                const float* arow = cb + (warp * 16 + rr * 8) * 32 + bh * 8;
                const float* wrow = WA + (ci * 128 + warp * 16 + rr * 8) * 16
                                       + jg * 4;

                #pragma unroll
                for (int kl = 0; kl < 8; ++kl) {
                    ulonglong2 a0 = *(const ulonglong2*)(arow + kl * 32);
                    ulonglong2 a1 = *(const ulonglong2*)(arow + kl * 32 + 4);
                    float4 wv     = *(const float4*)(wrow + kl * 16);
                    ull wp0 = pk2(wv.x);
                    ull wp1 = pk2(wv.y);
                    ull wp2 = pk2(wv.z);
                    ull wp3 = pk2(wv.w);
                    ffma2(acc[0],  a0.x, wp0);
                    ffma2(acc[1],  a0.y, wp0);
                    ffma2(acc[2],  a1.x, wp0);
                    ffma2(acc[3],  a1.y, wp0);
                    ffma2(acc[4],  a0.x, wp1);
                    ffma2(acc[5],  a0.y, wp1);
                    ffma2(acc[6],  a1.x, wp1);
                    ffma2(acc[7],  a1.y, wp1);
                    ffma2(acc[8],  a0.x, wp2);
                    ffma2(acc[9],  a0.y, wp2);
                    ffma2(acc[10], a1.x, wp2);
                    ffma2(acc[11], a1.y, wp2);
                    ffma2(acc[12], a0.x, wp3);
                    ffma2(acc[13], a0.y, wp3);
                    ffma2(acc[14], a1.x, wp3);
                    ffma2(acc[15], a1.y, wp3);
                }
            }

            // merge rr halves, then stash (rr=0 lanes only)
            #pragma unroll
            for (int i = 0; i < 16; ++i) acc[i] = red16(acc[i]);
            if (rr == 0) {
                float* rw = RED + warp * 512;
                #pragma unroll
                for (int cl = 0; cl < 4; ++cl) {
                    float* p = rw + (jg * 4 + cl) * 32 + bh * 8;
                    *(ulonglong2*)p       = make_ulonglong2(acc[cl*4],   acc[cl*4+1]);
                    *(ulonglong2*)(p + 4) = make_ulonglong2(acc[cl*4+2], acc[cl*4+3]);
                }
            }
        }
        __syncthreads();
        // cross-warp reduce + r update / p stash (512 outputs, 8-way)
        #pragma unroll
        for (int o = tid; o < 512; o += NTHR) {
            float s = 0.0f;
            #pragma unroll
            for (int w = 0; w < 8; ++w) s += RED[w * 512 + o];
            int j = o >> 5, b = o & 31;
            if (j < 8) {
                float g  = tanhf(s);
                float rn = 0.9f * Rs[o] + 0.1f * g;
                Rs[o] = rn;
                g_rT[(c8 + j) * 32 + b] = rn;
            } else {
                Ps[o - 256] = s;
            }
        }
        __threadfence();
        grid_barrier(epoch);   // r_new globally visible

        // ================= PHASE B =================
        // Z[32,8] = r_new(32x1024) @ WB(1024x8); 8 chunks of 128 rows.
        // Thread (rr,jg,bh): rows as A, cols jg*2..+1, batch bh*8..+7.
        {
            cp_chunk(ACT + ibuf * CH, g_rT + ciB(0) * CH, tid); ibuf = inc3(ibuf);
            cp_chunk(ACT + ibuf * CH, g_rT + ciB(1) * CH, tid); ibuf = inc3(ibuf);

            ull acc[8];                     // [cl 0..1][pair 0..3]
            #pragma unroll
            for (int i = 0; i < 8; ++i) acc[i] = 0ULL;

            #pragma unroll 1
            for (int c = 0; c < NCHB; ++c) {
                CP_WAIT1();
                __syncthreads();

                int nc = c + 2;
                if (nc < NCHB) {
                    cp_chunk(ACT + ibuf * CH, g_rT + ciB(nc) * CH, tid);
                    ibuf = inc3(ibuf);
                } else if (t + 1 < T_DIM) {
                    const float* nx = g_buf + (size_t)(t + 1) * (D_DIM * B_DIM);
                    cp_chunk(ACT + ibuf * CH, nx + ciA(nc - NCHB) * CH, tid);
                    ibuf = inc3(ibuf);
                } else {
                    CP_COMMIT_EMPTY();
                }

                int ci = ciB(c);
                const float* cb   = ACT + cbuf * CH;
                cbuf = inc3(cbuf);
                const float* arow = cb + (warp * 16 + rr * 8) * 32 + bh * 8;
                const float* wrow = WB + (ci * 128 + warp * 16 + rr * 8) * 8
                                       + jg * 2;

                #pragma unroll
                for (int kl = 0; kl < 8; ++kl) {
                    ulonglong2 a0 = *(const ulonglong2*)(arow + kl * 32);
                    ulonglong2 a1 = *(const ulonglong2*)(arow + kl * 32 + 4);
                    float2 wv     = *(const float2*)(wrow + kl * 8);
                    ull wp0 = pk2(wv.x);
                    ull wp1 = pk2(wv.y);
                    ffma2(acc[0], a0.x, wp0);
                    ffma2(acc[1], a0.y, wp0);
                    ffma2(acc[2], a1.x, wp0);
                    ffma2(acc[3], a1.y, wp0);
                    ffma2(acc[4], a0.x, wp1);
                    ffma2(acc[5], a0.y, wp1);
                    ffma2(acc[6], a1.x, wp1);
                    ffma2(acc[7], a1.y, wp1);
                }
            }

            #pragma unroll
            for (int i = 0; i < 8; ++i) acc[i] = red16(acc[i]);
            if (rr == 0) {
                float* rw = RED + warp * 256;
                #pragma unroll
                for (int cl = 0; cl < 2; ++cl) {
                    float* p = rw + (jg * 2 + cl) * 32 + bh * 8;
                    *(ulonglong2*)p       = make_ulonglong2(acc[cl*4],   acc[cl*4+1]);
                    *(ulonglong2*)(p + 4) = make_ulonglong2(acc[cl*4+2], acc[cl*4+3]);
                }
            }
        }
        __syncthreads();
        {
            float z = 0.0f;
            #pragma unroll
            for (int w = 0; w < 8; ++w) z += RED[w * 256 + tid];
            int j = tid >> 5, b = tid & 31;
            float hn = tanhf(Ps[tid] + z);
            g_hT[(c8 + j) * 32 + b] = hn;
            g_buf[(size_t)t * (D_DIM * B_DIM) + (c8 + j) * 32 + b] = hn;
        }
        __threadfence();
        grid_barrier(epoch);   // h_new visible before next step
    }
}

// ---------------------------------------------------------------------------
// Dummy kernel (ncu launch-index alignment so -s 5 -c 1 lands on scan_kernel)
// ---------------------------------------------------------------------------
__global__ void dummy_k(int v) { if (threadIdx.x == 0) g_dummy = v; }

// ---------------------------------------------------------------------------
// Transposes: x[b][t][k]  <->  buf[t][k][b]
// ---------------------------------------------------------------------------
__global__ void transpose_in(const float* __restrict__ x)
{
    __shared__ float s[32][65];
    const int t  = blockIdx.y;
    const int k0 = blockIdx.x * 64;
    const int tid = threadIdx.x;

    #pragma unroll
    for (int p = 0; p < 8; ++p) {
        int b  = p * 4 + (tid >> 6);
        int kk = tid & 63;
        s[b][kk] = x[(size_t)b * TD_STRIDE + (size_t)t * D_DIM + k0 + kk];
    }
    __syncthreads();
    #pragma unroll
    for (int p = 0; p < 8; ++p) {
        int kk = p * 8 + (tid >> 5);
        int b  = tid & 31;
        g_buf[(size_t)t * (D_DIM * B_DIM) + (size_t)(k0 + kk) * 32 + b] = s[b][kk];
    }
}

__global__ void transpose_out(float* __restrict__ out)
{
    __shared__ float s[64][33];
    const int t  = blockIdx.y;
    const int j0 = blockIdx.x * 64;
    const int tid = threadIdx.x;

    #pragma unroll
    for (int p = 0; p < 8; ++p) {
        int jj = p * 8 + (tid >> 5);
        int b  = tid & 31;
        s[jj][b] = g_buf[(size_t)t * (D_DIM * B_DIM) + (size_t)(j0 + jj) * 32 + b];
    }
    __syncthreads();
    #pragma unroll
    for (int p = 0; p < 8; ++p) {
        int b  = p * 4 + (tid >> 6);
        int jc = tid & 63;
        out[(size_t)b * TD_STRIDE + (size_t)t * D_DIM + j0 + jc] = s[jc][b];
    }
}

// ---------------------------------------------------------------------------
extern "C" void kernel_launch(void* const* d_in, const int* in_sizes, int n_in,
                              void* d_out, int out_size)
{
    const float* x   = (const float*)d_in[0];
    const float* Wxh = (const float*)d_in[1];
    const float* Whh = (const float*)d_in[2];
    const float* Wrh = (const float*)d_in[3];
    const float* Wxr = (const float*)d_in[4];
    const float* Whr = (const float*)d_in[5];
    float* out = (float*)d_out;

    cudaFuncSetAttribute(scan_kernel,
                         cudaFuncAttributeMaxDynamicSharedMemorySize,
                         SMEM_BYTES);

    dummy_k<<<1, 32>>>(1);
    dummy_k<<<1, 32>>>(2);
    transpose_in<<<dim3(16, 1024), NTHR>>>(x);
    scan_kernel<<<GRID_CTAS, NTHR, SMEM_BYTES>>>(Wxh, Whh, Wrh, Wxr, Whr, 0);
    scan_kernel<<<GRID_CTAS, NTHR, SMEM_BYTES>>>(Wxh, Whh, Wrh, Wxr, Whr, 1);
    transpose_out<<<dim3(16, 1024), NTHR>>>(out);
}